// round 6
// baseline (speedup 1.0000x reference)
#include <cuda_runtime.h>
#include <cuda_fp16.h>

#define S_LEN   2048
#define D_MODEL 1024
#define NHEAD   16
#define HDIM    64
#define BATCH   2

// Scratch (allocation-free rule: __device__ globals), all fp16
__device__ __half g_xh[(size_t)BATCH * S_LEN * D_MODEL];        // x in fp16
__device__ __half g_wqkvh[(size_t)3 * D_MODEL * D_MODEL];       // w_qkv in fp16
__device__ __half g_woh[(size_t)D_MODEL * D_MODEL];             // w_o in fp16
__device__ __half g_q [(size_t)BATCH * NHEAD * S_LEN * HDIM];   // [b][h][s][d]
__device__ __half g_k [(size_t)BATCH * NHEAD * S_LEN * HDIM];   // [b][h][s][d]
__device__ __half g_vt[(size_t)BATCH * NHEAD * HDIM * S_LEN];   // [b][h][d][s] (transposed!)
__device__ __half g_vals[(size_t)BATCH * S_LEN * D_MODEL];      // attention out

// ---------------------------------------------------------------------------
// Helpers
// ---------------------------------------------------------------------------
__device__ __forceinline__ void mma16(float* d, const unsigned* a, const unsigned* b) {
    asm volatile("mma.sync.aligned.m16n8k16.row.col.f32.f16.f16.f32 "
        "{%0,%1,%2,%3}, {%4,%5,%6,%7}, {%8,%9}, {%0,%1,%2,%3};"
        : "+f"(d[0]), "+f"(d[1]), "+f"(d[2]), "+f"(d[3])
        : "r"(a[0]), "r"(a[1]), "r"(a[2]), "r"(a[3]), "r"(b[0]), "r"(b[1]));
}
__device__ __forceinline__ unsigned pack2(float lo, float hi) {
    __half2 h = __floats2half2_rn(lo, hi);
    return *reinterpret_cast<unsigned*>(&h);
}
__device__ __forceinline__ void cp16(unsigned dst, const void* src) {
    asm volatile("cp.async.cg.shared.global [%0], [%1], 16;" :: "r"(dst), "l"(src) : "memory");
}
#define CP_COMMIT asm volatile("cp.async.commit_group;" ::: "memory")
#define CP_WAIT2  asm volatile("cp.async.wait_group 2;" ::: "memory")
#define CP_WAIT1  asm volatile("cp.async.wait_group 1;" ::: "memory")

// fp32 -> fp16 conversion pass (vectorized, n multiple of 4)
__global__ __launch_bounds__(256) void cvt_fp16(const float* __restrict__ src,
                                                __half* __restrict__ dst)
{
    int idx = blockIdx.x * 256 + threadIdx.x;
    float4 v = reinterpret_cast<const float4*>(src)[idx];
    __half2* d2 = reinterpret_cast<__half2*>(dst) + 2 * idx;
    d2[0] = __floats2half2_rn(v.x, v.y);
    d2[1] = __floats2half2_rn(v.z, v.w);
}

// ---------------------------------------------------------------------------
// fp16 GEMM core: C(128x128) = A(128xK) * B(128xK)^T, m16n8k16.
// 256 threads, 8 warps 2x4, warp tile 64x32, BK=32, 3-stage cp.async.
// smem stride 40 fp16 (80B) -> all LDS.32 fragment loads conflict-free.
// ---------------------------------------------------------------------------
#define HSTR 40
#define HSZ  (128 * HSTR)   // fp16 elems per matrix per stage

__device__ __forceinline__ void gemm_fp16_core(
    const __half* __restrict__ A, const __half* __restrict__ B, int K,
    int m0, int n0, float acc[4][4][4], __half* sm)
{
    __half* As = sm;             // [3][HSZ]
    __half* Bs = sm + 3 * HSZ;   // [3][HSZ]
    unsigned sA = (unsigned)__cvta_generic_to_shared(As);
    unsigned sB = (unsigned)__cvta_generic_to_shared(Bs);
    const int t = threadIdx.x;
    const int lane = t & 31, w = t >> 5;
    const int g = lane >> 2, cc = lane & 3;
    const int wm = w >> 2, wn = w & 3;

#pragma unroll
    for (int mt = 0; mt < 4; mt++)
#pragma unroll
        for (int nt = 0; nt < 4; nt++)
#pragma unroll
            for (int j = 0; j < 4; j++) acc[mt][nt][j] = 0.0f;

    auto issue = [&](int it, int st) {
        int k0 = it * 32;
#pragma unroll
        for (int i = 0; i < 2; i++) {
            int chunk = t + i * 256;          // 0..511 : 128 rows x 4 x 16B
            int row = chunk >> 2, c8 = (chunk & 3) << 3;
            cp16(sA + (unsigned)(st * HSZ + row * HSTR + c8) * 2u,
                 A + (size_t)(m0 + row) * K + k0 + c8);
            cp16(sB + (unsigned)(st * HSZ + row * HSTR + c8) * 2u,
                 B + (size_t)(n0 + row) * K + k0 + c8);
        }
    };

    const int NIT = K / 32;
    issue(0, 0); CP_COMMIT;
    issue(1, 1); CP_COMMIT;
    for (int it = 0; it < NIT; it++) {
        int st = it % 3;
        if (it + 2 < NIT) issue(it + 2, (it + 2) % 3);
        CP_COMMIT;                 // unconditional: keeps group count aligned
        CP_WAIT2;
        __syncthreads();
        const __half* as = As + st * HSZ;
        const __half* bs = Bs + st * HSZ;
#pragma unroll
        for (int kk = 0; kk < 32; kk += 16) {
            unsigned af[4][4], bf[4][2];
#pragma unroll
            for (int mt = 0; mt < 4; mt++) {
                int r = 64 * wm + 16 * mt + g;
                af[mt][0] = *reinterpret_cast<const unsigned*>(as + r * HSTR + kk + 2 * cc);
                af[mt][1] = *reinterpret_cast<const unsigned*>(as + (r + 8) * HSTR + kk + 2 * cc);
                af[mt][2] = *reinterpret_cast<const unsigned*>(as + r * HSTR + kk + 8 + 2 * cc);
                af[mt][3] = *reinterpret_cast<const unsigned*>(as + (r + 8) * HSTR + kk + 8 + 2 * cc);
            }
#pragma unroll
            for (int nt = 0; nt < 4; nt++) {
                int col = 32 * wn + 8 * nt + g;
                bf[nt][0] = *reinterpret_cast<const unsigned*>(bs + col * HSTR + kk + 2 * cc);
                bf[nt][1] = *reinterpret_cast<const unsigned*>(bs + col * HSTR + kk + 8 + 2 * cc);
            }
#pragma unroll
            for (int mt = 0; mt < 4; mt++)
#pragma unroll
                for (int nt = 0; nt < 4; nt++)
                    mma16(acc[mt][nt], af[mt], bf[nt]);
        }
        __syncthreads();
    }
}

// ---------------------------------------------------------------------------
// GEMM 1: qkv = x @ w_qkv^T + b_qkv -> g_q/g_k (row-major) and g_vt (transposed)
// ---------------------------------------------------------------------------
__global__ __launch_bounds__(256, 2) void gemm_qkv_tc(const float* __restrict__ bias)
{
    extern __shared__ __half smh[];
    float acc[4][4][4];
    const int m0 = blockIdx.y * 128, n0 = blockIdx.x * 128;
    gemm_fp16_core(g_xh, g_wqkvh, D_MODEL, m0, n0, acc, smh);

    const int lane = threadIdx.x & 31, w = threadIdx.x >> 5;
    const int g = lane >> 2, cc = lane & 3;
    const int wm = w >> 2, wn = w & 3;
#pragma unroll
    for (int mt = 0; mt < 4; mt++) {
#pragma unroll
        for (int nt = 0; nt < 4; nt++) {
            int n = n0 + 32 * wn + 8 * nt + 2 * cc;
            int h = n / 192;
            int r = n - h * 192;
            int part = r >> 6;
            int d = r & 63;
            float b0 = bias[n], b1 = bias[n + 1];
#pragma unroll
            for (int hi = 0; hi < 2; hi++) {
                int m = m0 + 64 * wm + 16 * mt + g + 8 * hi;
                int bb = m >> 11, s = m & 2047;
                float v0 = acc[mt][nt][2 * hi] + b0;
                float v1 = acc[mt][nt][2 * hi + 1] + b1;
                if (part == 2) {
                    // transposed: g_vt[b][h][d][s]
                    size_t off = (((size_t)bb * NHEAD + h) * HDIM + d) * S_LEN + s;
                    g_vt[off]          = __float2half_rn(v0);
                    g_vt[off + S_LEN]  = __float2half_rn(v1);
                } else {
                    size_t off = (((size_t)bb * NHEAD + h) * S_LEN + s) * HDIM + d;
                    __half2 hv = __floats2half2_rn(v0, v1);
                    *reinterpret_cast<__half2*>((part == 0 ? g_q : g_k) + off) = hv;
                }
            }
        }
    }
}

// ---------------------------------------------------------------------------
// GEMM 2: out = vals @ w_o^T + b_o  (fp32 output)
// ---------------------------------------------------------------------------
__global__ __launch_bounds__(256, 2) void gemm_o_tc(const float* __restrict__ bias,
                                                    float* __restrict__ out)
{
    extern __shared__ __half smh[];
    float acc[4][4][4];
    const int m0 = blockIdx.y * 128, n0 = blockIdx.x * 128;
    gemm_fp16_core(g_vals, g_woh, D_MODEL, m0, n0, acc, smh);

    const int lane = threadIdx.x & 31, w = threadIdx.x >> 5;
    const int g = lane >> 2, cc = lane & 3;
    const int wm = w >> 2, wn = w & 3;
#pragma unroll
    for (int mt = 0; mt < 4; mt++) {
#pragma unroll
        for (int nt = 0; nt < 4; nt++) {
            int n = n0 + 32 * wn + 8 * nt + 2 * cc;
            float b0 = bias[n], b1 = bias[n + 1];
#pragma unroll
            for (int hi = 0; hi < 2; hi++) {
                int m = m0 + 64 * wm + 16 * mt + g + 8 * hi;
                *reinterpret_cast<float2*>(out + (size_t)m * D_MODEL + n) =
                    make_float2(acc[mt][nt][2 * hi] + b0, acc[mt][nt][2 * hi + 1] + b1);
            }
        }
    }
}

// ---------------------------------------------------------------------------
// Flash attention, fp16 m16n8k16. Block = 128 q rows of one (b,h), 8 warps.
// Q frags in regs (pre-scaled 0.125). K [kv][d] and Vt [d][kv] tiles
// double-buffered via cp.async, stride 72 fp16 -> conflict-free LDS.32.
// P C-fragments repack DIRECTLY into A-fragments for P@V (no smem staging).
// ---------------------------------------------------------------------------
#define ASTR 72
#define ATILE (64 * ASTR)                       // fp16 elems per tile per stage
#define ATTN_SMEM_BYTES (2 * 2 * ATILE * 2)     // K+V, 2 stages, fp16 = 36864

__global__ __launch_bounds__(256, 2) void attn_tc()
{
    extern __shared__ __half smh[];
    __half* Ks = smh;                 // [2][64][ASTR]
    __half* Vs = smh + 2 * ATILE;     // [2][64][ASTR]
    unsigned sK = (unsigned)__cvta_generic_to_shared(Ks);
    unsigned sV = (unsigned)__cvta_generic_to_shared(Vs);

    const int t = threadIdx.x, lane = t & 31, w = t >> 5;
    const int g = lane >> 2, cc = lane & 3;
    const int q0 = blockIdx.x * 128;
    const size_t base = ((size_t)blockIdx.z * NHEAD + blockIdx.y) * S_LEN * HDIM;

    // Q fragments (4 ksteps of 16), scaled by 0.125 (exact in fp16)
    unsigned qf[4][4];
    const int r0 = q0 + 16 * w + g;
    {
        const __half* Qg = g_q + base;
        const __half2 sc = __floats2half2_rn(0.125f, 0.125f);
#pragma unroll
        for (int ks = 0; ks < 4; ks++) {
            int c = 16 * ks + 2 * cc;
            __half2 h0 = __hmul2(*reinterpret_cast<const __half2*>(Qg + (size_t)r0 * HDIM + c), sc);
            __half2 h1 = __hmul2(*reinterpret_cast<const __half2*>(Qg + (size_t)(r0 + 8) * HDIM + c), sc);
            __half2 h2 = __hmul2(*reinterpret_cast<const __half2*>(Qg + (size_t)r0 * HDIM + c + 8), sc);
            __half2 h3 = __hmul2(*reinterpret_cast<const __half2*>(Qg + (size_t)(r0 + 8) * HDIM + c + 8), sc);
            qf[ks][0] = *reinterpret_cast<unsigned*>(&h0);
            qf[ks][1] = *reinterpret_cast<unsigned*>(&h1);
            qf[ks][2] = *reinterpret_cast<unsigned*>(&h2);
            qf[ks][3] = *reinterpret_cast<unsigned*>(&h3);
        }
    }

    float o[8][4];
#pragma unroll
    for (int nt = 0; nt < 8; nt++)
#pragma unroll
        for (int j = 0; j < 4; j++) o[nt][j] = 0.0f;
    float mr0 = -1e30f, mr1 = -1e30f, lr0 = 0.0f, lr1 = 0.0f;

    auto issue = [&](int kt, int st) {
        const __half* kg  = g_k  + base + (size_t)kt * 64 * HDIM;   // [kv][d]
        const __half* vtg = g_vt + base;                            // [d][s]
#pragma unroll
        for (int i = 0; i < 2; i++) {
            int chunk = t + i * 256;           // 0..511 : 64 rows x 8 x 16B
            int row = chunk >> 3, c8 = (chunk & 7) << 3;
            cp16(sK + (unsigned)(st * ATILE + row * ASTR + c8) * 2u, kg + row * HDIM + c8);
            cp16(sV + (unsigned)(st * ATILE + row * ASTR + c8) * 2u,
                 vtg + (size_t)row * S_LEN + kt * 64 + c8);
        }
    };

    const int NT = S_LEN / 64;
    issue(0, 0); CP_COMMIT;
    for (int kt = 0; kt < NT; kt++) {
        int st = kt & 1;
        if (kt + 1 < NT) issue(kt + 1, st ^ 1);
        CP_COMMIT;                 // unconditional
        CP_WAIT1;
        __syncthreads();

        const __half* kp = Ks + st * ATILE;
        const __half* vp = Vs + st * ATILE;

        // Scores: S = (Q*0.125) @ K^T  (warp: 16 rows x 64 kv)
        float s[8][4];
#pragma unroll
        for (int nt = 0; nt < 8; nt++)
#pragma unroll
            for (int j = 0; j < 4; j++) s[nt][j] = 0.0f;
#pragma unroll
        for (int ks = 0; ks < 4; ks++) {
#pragma unroll
            for (int nt = 0; nt < 8; nt++) {
                unsigned bf[2];
                const __half* kr = kp + (8 * nt + g) * ASTR + 16 * ks + 2 * cc;
                bf[0] = *reinterpret_cast<const unsigned*>(kr);
                bf[1] = *reinterpret_cast<const unsigned*>(kr + 8);
                mma16(s[nt], qf[ks], bf);
            }
        }

        // Online softmax (rows g and g+8; quad = 4 lanes)
        float mx0 = -1e30f, mx1 = -1e30f;
#pragma unroll
        for (int nt = 0; nt < 8; nt++) {
            mx0 = fmaxf(mx0, fmaxf(s[nt][0], s[nt][1]));
            mx1 = fmaxf(mx1, fmaxf(s[nt][2], s[nt][3]));
        }
        mx0 = fmaxf(mx0, __shfl_xor_sync(0xffffffffu, mx0, 1));
        mx0 = fmaxf(mx0, __shfl_xor_sync(0xffffffffu, mx0, 2));
        mx1 = fmaxf(mx1, __shfl_xor_sync(0xffffffffu, mx1, 1));
        mx1 = fmaxf(mx1, __shfl_xor_sync(0xffffffffu, mx1, 2));
        float mn0 = fmaxf(mr0, mx0), mn1 = fmaxf(mr1, mx1);
        float cr0 = __expf(mr0 - mn0), cr1 = __expf(mr1 - mn1);
        mr0 = mn0; mr1 = mn1;
        float sum0 = 0.0f, sum1 = 0.0f;
#pragma unroll
        for (int nt = 0; nt < 8; nt++) {
            s[nt][0] = __expf(s[nt][0] - mn0); sum0 += s[nt][0];
            s[nt][1] = __expf(s[nt][1] - mn0); sum0 += s[nt][1];
            s[nt][2] = __expf(s[nt][2] - mn1); sum1 += s[nt][2];
            s[nt][3] = __expf(s[nt][3] - mn1); sum1 += s[nt][3];
        }
        sum0 += __shfl_xor_sync(0xffffffffu, sum0, 1);
        sum0 += __shfl_xor_sync(0xffffffffu, sum0, 2);
        sum1 += __shfl_xor_sync(0xffffffffu, sum1, 1);
        sum1 += __shfl_xor_sync(0xffffffffu, sum1, 2);
        lr0 = lr0 * cr0 + sum0;
        lr1 = lr1 * cr1 + sum1;
#pragma unroll
        for (int nt = 0; nt < 8; nt++) {
            o[nt][0] *= cr0; o[nt][1] *= cr0; o[nt][2] *= cr1; o[nt][3] *= cr1;
        }

        // Repack P C-frags directly into A-frags (no smem!), then O += P @ V
#pragma unroll
        for (int ks = 0; ks < 4; ks++) {
            unsigned af[4];
            af[0] = pack2(s[2 * ks][0],     s[2 * ks][1]);
            af[1] = pack2(s[2 * ks][2],     s[2 * ks][3]);
            af[2] = pack2(s[2 * ks + 1][0], s[2 * ks + 1][1]);
            af[3] = pack2(s[2 * ks + 1][2], s[2 * ks + 1][3]);
#pragma unroll
            for (int nt = 0; nt < 8; nt++) {
                unsigned bf[2];
                const __half* vr = vp + (8 * nt + g) * ASTR + 16 * ks + 2 * cc;
                bf[0] = *reinterpret_cast<const unsigned*>(vr);
                bf[1] = *reinterpret_cast<const unsigned*>(vr + 8);
                mma16(o[nt], af, bf);
            }
        }
        __syncthreads();
    }

    // Normalize, write g_vals (fp16) at [b][s][h*64+d]
    float inv0 = 1.0f / lr0, inv1 = 1.0f / lr1;
    __half* Og = g_vals + ((size_t)blockIdx.z * S_LEN) * D_MODEL + blockIdx.y * HDIM;
#pragma unroll
    for (int nt = 0; nt < 8; nt++) {
        int col = 8 * nt + 2 * cc;
        *reinterpret_cast<__half2*>(Og + (size_t)r0 * D_MODEL + col) =
            __floats2half2_rn(o[nt][0] * inv0, o[nt][1] * inv0);
        *reinterpret_cast<__half2*>(Og + (size_t)(r0 + 8) * D_MODEL + col) =
            __floats2half2_rn(o[nt][2] * inv1, o[nt][3] * inv1);
    }
}

// ---------------------------------------------------------------------------
// Launch
// ---------------------------------------------------------------------------
extern "C" void kernel_launch(void* const* d_in, const int* in_sizes, int n_in,
                              void* d_out, int out_size)
{
    const float* x     = (const float*)d_in[0];
    const float* w_qkv = (const float*)d_in[1];
    const float* b_qkv = (const float*)d_in[2];
    const float* w_o   = (const float*)d_in[3];
    const float* b_o   = (const float*)d_in[4];
    float* out = (float*)d_out;

    const int gemm_smem = 6 * HSZ * (int)sizeof(__half);    // 61440
    cudaFuncSetAttribute(gemm_qkv_tc, cudaFuncAttributeMaxDynamicSharedMemorySize, gemm_smem);
    cudaFuncSetAttribute(gemm_o_tc,   cudaFuncAttributeMaxDynamicSharedMemorySize, gemm_smem);

    __half* xh;  cudaGetSymbolAddress((void**)&xh,  g_xh);
    __half* wqh; cudaGetSymbolAddress((void**)&wqh, g_wqkvh);
    __half* woh; cudaGetSymbolAddress((void**)&woh, g_woh);

    // fp32 -> fp16 pre-conversion
    cvt_fp16<<<(BATCH * S_LEN * D_MODEL) / 1024, 256>>>(x, xh);
    cvt_fp16<<<(3 * D_MODEL * D_MODEL) / 1024, 256>>>(w_qkv, wqh);
    cvt_fp16<<<(D_MODEL * D_MODEL) / 1024, 256>>>(w_o, woh);

    // QKV projection: N=3072 -> 24 tiles, M=4096 -> 32 tiles
    gemm_qkv_tc<<<dim3(24, 32), 256, gemm_smem>>>(b_qkv);

    // Attention: 16 q-tiles x 16 heads x 2 batches
    attn_tc<<<dim3(S_LEN / 128, NHEAD, BATCH), 256, ATTN_SMEM_BYTES>>>();

    // Output projection: N=1024 -> 8 tiles, M=4096 -> 32 tiles
    gemm_o_tc<<<dim3(8, 32), 256, gemm_smem>>>(b_o, out);
}